// round 10
// baseline (speedup 1.0000x reference)
#include <cuda_runtime.h>
#include <cuda_bf16.h>

// Problem dims (fixed by the dataset)
#define BB   4
#define TQ   256
#define TV   1024
#define DD   512
#define AA   128

// Scratch buffers (device globals: allocation-free)
__device__ float g_K[BB * TV * AA];      // 2 MB
__device__ float g_Q[BB * TQ * AA];      // 0.5 MB
__device__ float g_attn[BB * TQ * TV];   // 4 MB

// ---------------------------------------------------------------------------
// fast math helpers
// ---------------------------------------------------------------------------
__device__ __forceinline__ float fast_ex2(float x) {
    float y;
    asm("ex2.approx.f32 %0, %1;" : "=f"(y) : "f"(x));
    return y;
}
__device__ __forceinline__ float ftanh(float x) {
    float y;
    asm("tanh.approx.f32 %0, %1;" : "=f"(y) : "f"(x));
    return y;
}

// ---------------------------------------------------------------------------
// Kernel A: fused K/Q projection, double-buffered, 512 threads.
// out[M,128] = X[M,512] @ W[512,128] + b
// BM=32, BN=128, BK=32, 512 threads, micro 2x4 -> 16 warps/SM for latency.
// grid = BB*TV/32 + BB*TQ/32 = 128 + 32 = 160 CTAs (one wave).
// ---------------------------------------------------------------------------
#define PROJ_KBLKS ((BB * TV) / 32)   // 128
#define PROJ_NTILES (DD / 32)         // 16

__global__ void __launch_bounds__(512) proj_kernel(
    const float* __restrict__ inputs, const float* __restrict__ context,
    const float* __restrict__ Wk, const float* __restrict__ bk,
    const float* __restrict__ Wq, const float* __restrict__ bq)
{
    __shared__ float Xs[2][32][32];
    __shared__ float Ws[2][32][128];

    const int bx = blockIdx.x;
    const bool isK = (bx < PROJ_KBLKS);
    const float* X    = isK ? inputs : context;
    const float* W    = isK ? Wk : Wq;
    const float* bias = isK ? bk : bq;
    float* out        = isK ? g_K : g_Q;
    const int r0 = (isK ? bx : (bx - PROJ_KBLKS)) * 32;

    const int t  = threadIdx.x;
    const int tx = t & 31;        // col group: cols tx*4 .. tx*4+3
    const int ty = t >> 5;        // row group: rows ty*2, ty*2+1 (16 groups)

    // fill coordinates
    const int xr = t >> 3, xc4 = (t & 7) * 4;      // Xs: 1 float4 (t<256)
    const int wr = t >> 5, wc4 = (t & 31) * 4;     // Ws: 2 float4 (+16 rows)

    float acc[2][4] = {};

    // prologue: tile 0 -> buffer 0
    {
        if (t < 256)
            *(float4*)&Xs[0][xr][xc4] =
                *(const float4*)&X[(size_t)(r0 + xr) * DD + xc4];
        *(float4*)&Ws[0][wr][wc4] =
            *(const float4*)&W[(size_t)(wr) * AA + wc4];
        *(float4*)&Ws[0][wr + 16][wc4] =
            *(const float4*)&W[(size_t)(wr + 16) * AA + wc4];
    }
    __syncthreads();

    for (int kt = 0; kt < PROJ_NTILES; ++kt) {
        const int cur = kt & 1;
        float4 pX, pW0, pW1;
        const bool has_next = (kt + 1 < PROJ_NTILES);
        if (has_next) {          // prefetch next tile into registers
            const int k0 = (kt + 1) * 32;
            if (t < 256)
                pX = *(const float4*)&X[(size_t)(r0 + xr) * DD + k0 + xc4];
            pW0 = *(const float4*)&W[(size_t)(k0 + wr) * AA + wc4];
            pW1 = *(const float4*)&W[(size_t)(k0 + wr + 16) * AA + wc4];
        }
#pragma unroll
        for (int k4 = 0; k4 < 32; k4 += 4) {
            float4 xv0 = *(const float4*)&Xs[cur][ty * 2 + 0][k4];
            float4 xv1 = *(const float4*)&Xs[cur][ty * 2 + 1][k4];
#pragma unroll
            for (int kk = 0; kk < 4; ++kk) {
                float4 wv = *(const float4*)&Ws[cur][k4 + kk][tx * 4];
                float x0 = (&xv0.x)[kk], x1 = (&xv1.x)[kk];
                acc[0][0] = fmaf(x0, wv.x, acc[0][0]);
                acc[0][1] = fmaf(x0, wv.y, acc[0][1]);
                acc[0][2] = fmaf(x0, wv.z, acc[0][2]);
                acc[0][3] = fmaf(x0, wv.w, acc[0][3]);
                acc[1][0] = fmaf(x1, wv.x, acc[1][0]);
                acc[1][1] = fmaf(x1, wv.y, acc[1][1]);
                acc[1][2] = fmaf(x1, wv.z, acc[1][2]);
                acc[1][3] = fmaf(x1, wv.w, acc[1][3]);
            }
        }
        if (has_next) {
            const int nxt = cur ^ 1;
            *(float4*)&Ws[nxt][wr][wc4] = pW0;
            *(float4*)&Ws[nxt][wr + 16][wc4] = pW1;
            if (t < 256) *(float4*)&Xs[nxt][xr][xc4] = pX;
            __syncthreads();
        }
    }

    float b0 = bias[tx * 4 + 0], b1 = bias[tx * 4 + 1];
    float b2 = bias[tx * 4 + 2], b3 = bias[tx * 4 + 3];
#pragma unroll
    for (int r = 0; r < 2; ++r) {
        float4 o;
        o.x = acc[r][0] + b0; o.y = acc[r][1] + b1;
        o.z = acc[r][2] + b2; o.w = acc[r][3] + b3;
        *(float4*)&out[(size_t)(r0 + ty * 2 + r) * AA + tx * 4] = o;
    }
}

// ---------------------------------------------------------------------------
// Kernel B: scores + softmax, transpose-free K layout.
// grid: (TQ/4, B), 256 threads, 2 CTAs/SM.
// Ks[v][a] v-major, row stride 132 floats (33x16B): float4 fills are
// coalesced+conflict-free; per-thread float4 reads over a are conflict-free
// across v (chunk bank = 33v = v mod 32). q/attn_v reads are broadcasts.
// score[q,v] = sum_a attn_v[a] * tanh(Q[q,a] + K[v,a]), then masked softmax.
// ---------------------------------------------------------------------------
#define KS_STRIDE 132
#define SMEMB_FLOATS (128 * KS_STRIDE + 4 * 128 + 128 + 4 * 1024)

__global__ void __launch_bounds__(256, 2) score_softmax_kernel(
    const int* __restrict__ mask, const float* __restrict__ attn_v)
{
    extern __shared__ float sm[];
    float* Ks  = sm;                         // 128*132 (v-major, padded)
    float* Qs  = Ks + 128 * KS_STRIDE;       // 512
    float* av  = Qs + 4 * 128;               // 128
    float* sc  = av + 128;                   // 4096

    const int t  = threadIdx.x;
    const int b  = blockIdx.y;
    const int q0 = blockIdx.x * 4;

    if (t < 128) {
        *(float4*)&Qs[t * 4] =
            *(const float4*)&g_Q[((size_t)(b * TQ + q0)) * AA + t * 4];
        av[t] = attn_v[t];
    }

    const int v0 = t & 63;         // this thread's v and v+64
    const int q  = t >> 6;         // 0..3

    for (int vt = 0; vt < TV / 128; ++vt) {
        const int vbase = vt * 128;
        __syncthreads();   // protect Ks reads (and first-iter Qs/av writes)
        // fill Ks[v][a] straight from g_K (no transpose): 4096 float4 total
        const float* Kp = g_K + ((size_t)b * TV + vbase) * AA;
#pragma unroll
        for (int i = 0; i < 16; ++i) {
            int f = i * 256 + t;
            int row = f >> 5, c4 = (f & 31) * 4;
            *(float4*)&Ks[row * KS_STRIDE + c4] =
                *(const float4*)&Kp[(size_t)row * AA + c4];
        }
        __syncthreads();

        float a0 = 0.f, a1 = 0.f;
        const float* k0p = Ks + v0 * KS_STRIDE;
        const float* k1p = Ks + (v0 + 64) * KS_STRIDE;
        const float* qp  = Qs + q * AA;
#pragma unroll 4
        for (int a4 = 0; a4 < AA; a4 += 4) {
            float4 k0 = *(const float4*)&k0p[a4];
            float4 k1 = *(const float4*)&k1p[a4];
            float4 q4 = *(const float4*)&qp[a4];
            float4 w4 = *(const float4*)&av[a4];
            a0 = fmaf(w4.x, ftanh(q4.x + k0.x), a0);
            a1 = fmaf(w4.x, ftanh(q4.x + k1.x), a1);
            a0 = fmaf(w4.y, ftanh(q4.y + k0.y), a0);
            a1 = fmaf(w4.y, ftanh(q4.y + k1.y), a1);
            a0 = fmaf(w4.z, ftanh(q4.z + k0.z), a0);
            a1 = fmaf(w4.z, ftanh(q4.z + k1.z), a1);
            a0 = fmaf(w4.w, ftanh(q4.w + k0.w), a0);
            a1 = fmaf(w4.w, ftanh(q4.w + k1.w), a1);
        }
        sc[q * TV + vbase + v0]      = a0;
        sc[q * TV + vbase + v0 + 64] = a1;
    }
    __syncthreads();

    const int w = t >> 5, lane = t & 31;
    if (w < 4) {
        float* row = sc + w * TV;
        const int* mrow = mask + (size_t)b * TV;
        float mx = -3.4e38f;
        for (int j = lane; j < TV; j += 32) {
            float s = row[j] + (1.0f - (float)mrow[j]) * (-1e9f);
            row[j] = s;
            mx = fmaxf(mx, s);
        }
#pragma unroll
        for (int o = 16; o; o >>= 1) mx = fmaxf(mx, __shfl_xor_sync(~0u, mx, o));
        float sum = 0.f;
        for (int j = lane; j < TV; j += 32) {
            float e = fast_ex2((row[j] - mx) * 1.4426950408889634f);
            row[j] = e;
            sum += e;
        }
#pragma unroll
        for (int o = 16; o; o >>= 1) sum += __shfl_xor_sync(~0u, sum, o);
        float inv = 1.0f / sum;
        float* arow = g_attn + ((size_t)(b * TQ + q0 + w)) * TV;
        for (int j = lane; j < TV; j += 32) arow[j] = row[j] * inv;
    }
}

// ---------------------------------------------------------------------------
// Kernel C: out[b,q,d] = sum_v attn[b,q,v] * inputs[b,v,d]
// double-buffered, k-vectorized LDS (unchanged from R7).
// BM=32(q), BN=64(d), BK=32(v), 256 threads, micro 2x4.
// grid: (8, 8, 4) = 256 CTAs -> 2 co-resident per SM.
// ---------------------------------------------------------------------------
__global__ void __launch_bounds__(256) av_kernel(
    const float* __restrict__ inp, float* __restrict__ out)
{
    __shared__ float As[2][32][36];   // stride 36: float4-aligned fills
    __shared__ float Is[2][32][64];

    const int t  = threadIdx.x;
    const int tx = t & 15;        // col group: cols tx*4 .. tx*4+3 (of 64)
    const int ty = t >> 4;        // row group: rows ty*2, ty*2+1 (of 32)
    const int b  = blockIdx.z;
    const int q0 = blockIdx.y * 32;
    const int d0 = blockIdx.x * 64;

    const int ar = t >> 3, ac4 = (t & 7) * 4;      // As: 1 float4/thread
    const int ir = t >> 4, ic4 = (t & 15) * 4;     // Is: 2 float4/thread

    float acc[2][4] = {};

    {
        *(float4*)&As[0][ar][ac4] =
            *(const float4*)&g_attn[((size_t)(b * TQ + q0 + ar)) * TV + ac4];
        *(float4*)&Is[0][ir][ic4] =
            *(const float4*)&inp[((size_t)(b * TV + ir)) * DD + d0 + ic4];
        *(float4*)&Is[0][ir + 16][ic4] =
            *(const float4*)&inp[((size_t)(b * TV + ir + 16)) * DD + d0 + ic4];
    }
    __syncthreads();

    for (int vt = 0; vt < TV / 32; ++vt) {
        const int cur = vt & 1;
        const bool has_next = (vt + 1 < TV / 32);
        float4 pA, pI0, pI1;
        if (has_next) {
            const int v0 = (vt + 1) * 32;
            pA  = *(const float4*)&g_attn[((size_t)(b * TQ + q0 + ar)) * TV + v0 + ac4];
            pI0 = *(const float4*)&inp[((size_t)(b * TV + v0 + ir)) * DD + d0 + ic4];
            pI1 = *(const float4*)&inp[((size_t)(b * TV + v0 + ir + 16)) * DD + d0 + ic4];
        }
#pragma unroll
        for (int k4 = 0; k4 < 32; k4 += 4) {
            float4 a0 = *(const float4*)&As[cur][ty * 2 + 0][k4];
            float4 a1 = *(const float4*)&As[cur][ty * 2 + 1][k4];
#pragma unroll
            for (int kk = 0; kk < 4; ++kk) {
                float4 iv = *(const float4*)&Is[cur][k4 + kk][tx * 4];
                float av0 = (&a0.x)[kk], av1 = (&a1.x)[kk];
                acc[0][0] = fmaf(av0, iv.x, acc[0][0]);
                acc[0][1] = fmaf(av0, iv.y, acc[0][1]);
                acc[0][2] = fmaf(av0, iv.z, acc[0][2]);
                acc[0][3] = fmaf(av0, iv.w, acc[0][3]);
                acc[1][0] = fmaf(av1, iv.x, acc[1][0]);
                acc[1][1] = fmaf(av1, iv.y, acc[1][1]);
                acc[1][2] = fmaf(av1, iv.z, acc[1][2]);
                acc[1][3] = fmaf(av1, iv.w, acc[1][3]);
            }
        }
        if (has_next) {
            const int nxt = cur ^ 1;
            *(float4*)&As[nxt][ar][ac4] = pA;
            *(float4*)&Is[nxt][ir][ic4] = pI0;
            *(float4*)&Is[nxt][ir + 16][ic4] = pI1;
            __syncthreads();
        }
    }

#pragma unroll
    for (int r = 0; r < 2; ++r) {
        float4 o;
        o.x = acc[r][0]; o.y = acc[r][1]; o.z = acc[r][2]; o.w = acc[r][3];
        *(float4*)&out[((size_t)(b * TQ + q0 + ty * 2 + r)) * DD + d0 + tx * 4] = o;
    }
}

// ---------------------------------------------------------------------------
extern "C" void kernel_launch(void* const* d_in, const int* in_sizes, int n_in,
                              void* d_out, int out_size)
{
    (void)in_sizes; (void)n_in; (void)out_size;
    const float* inputs  = (const float*)d_in[0];   // [B,Tv,D]
    const float* context = (const float*)d_in[1];   // [B,Tq,D]
    const int*   mask    = (const int*)  d_in[2];   // [B,Tv]
    const float* Wk      = (const float*)d_in[3];   // [D,A]
    const float* bk      = (const float*)d_in[4];   // [A]
    const float* Wq      = (const float*)d_in[5];   // [D,A]
    const float* bq      = (const float*)d_in[6];   // [A]
    const float* attn_v  = (const float*)d_in[7];   // [A]
    float* out = (float*)d_out;                     // [B,Tq,D]

    static const size_t smemB = SMEMB_FLOATS * sizeof(float);
    cudaFuncSetAttribute(score_softmax_kernel,
                         cudaFuncAttributeMaxDynamicSharedMemorySize, (int)smemB);

    // K = inputs @ Wk + bk ; Q = context @ Wq + bq  (fused, 160 CTAs x 512 thr)
    proj_kernel<<<PROJ_KBLKS + (BB * TQ) / 32, 512>>>(
        inputs, context, Wk, bk, Wq, bq);
    // scores + softmax -> g_attn
    {
        dim3 grid(TQ / 4, BB);
        score_softmax_kernel<<<grid, 256, smemB>>>(mask, attn_v);
    }
    // out = attn @ inputs
    {
        dim3 grid(DD / 64, TQ / 32, BB);
        av_kernel<<<grid, 256>>>(inputs, out);
    }
}

// round 12
// speedup vs baseline: 1.2604x; 1.2604x over previous
#include <cuda_runtime.h>
#include <cuda_bf16.h>
#include <cstdint>

// Problem dims (fixed by the dataset)
#define BB   4
#define TQ   256
#define TV   1024
#define DD   512
#define AA   128

// Scratch buffers (device globals: allocation-free)
__device__ float g_K[BB * TV * AA];      // 2 MB
__device__ float g_Q[BB * TQ * AA];      // 0.5 MB
__device__ float g_attn[BB * TQ * TV];   // 4 MB

// ---------------------------------------------------------------------------
// fast math helpers
// ---------------------------------------------------------------------------
__device__ __forceinline__ float fast_ex2(float x) {
    float y;
    asm("ex2.approx.f32 %0, %1;" : "=f"(y) : "f"(x));
    return y;
}
__device__ __forceinline__ float ftanh(float x) {
    float y;
    asm("tanh.approx.f32 %0, %1;" : "=f"(y) : "f"(x));
    return y;
}
// cp.async helpers (16B)
__device__ __forceinline__ void cp16(void* dst_smem, const void* src_gmem) {
    unsigned d = (unsigned)__cvta_generic_to_shared(dst_smem);
    asm volatile("cp.async.ca.shared.global [%0], [%1], 16;" :: "r"(d), "l"(src_gmem));
}
__device__ __forceinline__ void cp_commit() {
    asm volatile("cp.async.commit_group;");
}
__device__ __forceinline__ void cp_wait0() {
    asm volatile("cp.async.wait_group 0;");
}

// ---------------------------------------------------------------------------
// Kernel A: fused K/Q projection, cp.async double-buffered.
// out[M,128] = X[M,512] @ W[512,128] + b
// BM=16, BN=128, BK=32, 128 threads, micro 4x4 (16 acc).
// grid = (BB*TV + BB*TQ)/16 = 320 CTAs -> 2-4 co-resident per SM
// (kills the 1.08-wave tail that capped the 160-CTA versions).
// ---------------------------------------------------------------------------
#define PROJ_KBLKS ((BB * TV) / 16)   // 256
#define PROJ_NTILES (DD / 32)         // 16

__global__ void __launch_bounds__(128) proj_kernel(
    const float* __restrict__ inputs, const float* __restrict__ context,
    const float* __restrict__ Wk, const float* __restrict__ bk,
    const float* __restrict__ Wq, const float* __restrict__ bq)
{
    __shared__ float Xs[2][16][32];
    __shared__ float Ws[2][32][128];

    const int bx = blockIdx.x;
    const bool isK = (bx < PROJ_KBLKS);
    const float* X    = isK ? inputs : context;
    const float* W    = isK ? Wk : Wq;
    const float* bias = isK ? bk : bq;
    float* out        = isK ? g_K : g_Q;
    const int r0 = (isK ? bx : (bx - PROJ_KBLKS)) * 16;

    const int t  = threadIdx.x;
    const int tx = t & 31;        // col group: cols tx*4 .. tx*4+3
    const int ty = t >> 5;        // row group: rows ty*4 .. ty*4+3 (of 16)

    // fill coordinates
    const int xr = t >> 3, xc4 = (t & 7) * 4;      // Xs: 16x32 = 128 float4

    float acc[4][4] = {};

    // prologue: tile 0 -> buffer 0
    {
        cp16(&Xs[0][xr][xc4], &X[(size_t)(r0 + xr) * DD + xc4]);
#pragma unroll
        for (int i = 0; i < 8; ++i) {           // Ws: 32x128 = 1024 float4
            int f = i * 128 + t;
            int rr = f >> 5, c4 = (f & 31) * 4;
            cp16(&Ws[0][rr][c4], &W[(size_t)rr * AA + c4]);
        }
        cp_commit();
        cp_wait0();
    }
    __syncthreads();

    for (int kt = 0; kt < PROJ_NTILES; ++kt) {
        const int cur = kt & 1;
        const bool has_next = (kt + 1 < PROJ_NTILES);
        if (has_next) {   // async-fill next buffer (reads of it drained at
                          // the barrier that ended the previous iteration)
            const int k0 = (kt + 1) * 32;
            const int nxt = cur ^ 1;
            cp16(&Xs[nxt][xr][xc4], &X[(size_t)(r0 + xr) * DD + k0 + xc4]);
#pragma unroll
            for (int i = 0; i < 8; ++i) {
                int f = i * 128 + t;
                int rr = f >> 5, c4 = (f & 31) * 4;
                cp16(&Ws[nxt][rr][c4], &W[(size_t)(k0 + rr) * AA + c4]);
            }
            cp_commit();
        }
#pragma unroll
        for (int k4 = 0; k4 < 32; k4 += 4) {
            float4 xv[4];
#pragma unroll
            for (int r = 0; r < 4; ++r)
                xv[r] = *(const float4*)&Xs[cur][ty * 4 + r][k4];
#pragma unroll
            for (int kk = 0; kk < 4; ++kk) {
                float4 wv = *(const float4*)&Ws[cur][k4 + kk][tx * 4];
#pragma unroll
                for (int r = 0; r < 4; ++r) {
                    float xs = (&xv[r].x)[kk];
                    acc[r][0] = fmaf(xs, wv.x, acc[r][0]);
                    acc[r][1] = fmaf(xs, wv.y, acc[r][1]);
                    acc[r][2] = fmaf(xs, wv.z, acc[r][2]);
                    acc[r][3] = fmaf(xs, wv.w, acc[r][3]);
                }
            }
        }
        if (has_next) {
            cp_wait0();
            __syncthreads();
        }
    }

    float b0 = bias[tx * 4 + 0], b1 = bias[tx * 4 + 1];
    float b2 = bias[tx * 4 + 2], b3 = bias[tx * 4 + 3];
#pragma unroll
    for (int r = 0; r < 4; ++r) {
        float4 o;
        o.x = acc[r][0] + b0; o.y = acc[r][1] + b1;
        o.z = acc[r][2] + b2; o.w = acc[r][3] + b3;
        *(float4*)&out[(size_t)(r0 + ty * 4 + r) * AA + tx * 4] = o;
    }
}

// ---------------------------------------------------------------------------
// Kernel B: scores + softmax, transpose-free K layout (unchanged from R10).
// grid: (TQ/4, B), 256 threads, 2 CTAs/SM.
// ---------------------------------------------------------------------------
#define KS_STRIDE 132
#define SMEMB_FLOATS (128 * KS_STRIDE + 4 * 128 + 128 + 4 * 1024)

__global__ void __launch_bounds__(256, 2) score_softmax_kernel(
    const int* __restrict__ mask, const float* __restrict__ attn_v)
{
    extern __shared__ float sm[];
    float* Ks  = sm;                         // 128*132 (v-major, padded)
    float* Qs  = Ks + 128 * KS_STRIDE;       // 512
    float* av  = Qs + 4 * 128;               // 128
    float* sc  = av + 128;                   // 4096

    const int t  = threadIdx.x;
    const int b  = blockIdx.y;
    const int q0 = blockIdx.x * 4;

    if (t < 128) {
        *(float4*)&Qs[t * 4] =
            *(const float4*)&g_Q[((size_t)(b * TQ + q0)) * AA + t * 4];
        av[t] = attn_v[t];
    }

    const int v0 = t & 63;         // this thread's v and v+64
    const int q  = t >> 6;         // 0..3

    for (int vt = 0; vt < TV / 128; ++vt) {
        const int vbase = vt * 128;
        __syncthreads();
        const float* Kp = g_K + ((size_t)b * TV + vbase) * AA;
#pragma unroll
        for (int i = 0; i < 16; ++i) {
            int f = i * 256 + t;
            int row = f >> 5, c4 = (f & 31) * 4;
            *(float4*)&Ks[row * KS_STRIDE + c4] =
                *(const float4*)&Kp[(size_t)row * AA + c4];
        }
        __syncthreads();

        float a0 = 0.f, a1 = 0.f;
        const float* k0p = Ks + v0 * KS_STRIDE;
        const float* k1p = Ks + (v0 + 64) * KS_STRIDE;
        const float* qp  = Qs + q * AA;
#pragma unroll 4
        for (int a4 = 0; a4 < AA; a4 += 4) {
            float4 k0 = *(const float4*)&k0p[a4];
            float4 k1 = *(const float4*)&k1p[a4];
            float4 q4 = *(const float4*)&qp[a4];
            float4 w4 = *(const float4*)&av[a4];
            a0 = fmaf(w4.x, ftanh(q4.x + k0.x), a0);
            a1 = fmaf(w4.x, ftanh(q4.x + k1.x), a1);
            a0 = fmaf(w4.y, ftanh(q4.y + k0.y), a0);
            a1 = fmaf(w4.y, ftanh(q4.y + k1.y), a1);
            a0 = fmaf(w4.z, ftanh(q4.z + k0.z), a0);
            a1 = fmaf(w4.z, ftanh(q4.z + k1.z), a1);
            a0 = fmaf(w4.w, ftanh(q4.w + k0.w), a0);
            a1 = fmaf(w4.w, ftanh(q4.w + k1.w), a1);
        }
        sc[q * TV + vbase + v0]      = a0;
        sc[q * TV + vbase + v0 + 64] = a1;
    }
    __syncthreads();

    const int w = t >> 5, lane = t & 31;
    if (w < 4) {
        float* row = sc + w * TV;
        const int* mrow = mask + (size_t)b * TV;
        float mx = -3.4e38f;
        for (int j = lane; j < TV; j += 32) {
            float s = row[j] + (1.0f - (float)mrow[j]) * (-1e9f);
            row[j] = s;
            mx = fmaxf(mx, s);
        }
#pragma unroll
        for (int o = 16; o; o >>= 1) mx = fmaxf(mx, __shfl_xor_sync(~0u, mx, o));
        float sum = 0.f;
        for (int j = lane; j < TV; j += 32) {
            float e = fast_ex2((row[j] - mx) * 1.4426950408889634f);
            row[j] = e;
            sum += e;
        }
#pragma unroll
        for (int o = 16; o; o >>= 1) sum += __shfl_xor_sync(~0u, sum, o);
        float inv = 1.0f / sum;
        float* arow = g_attn + ((size_t)(b * TQ + q0 + w)) * TV;
        for (int j = lane; j < TV; j += 32) arow[j] = row[j] * inv;
    }
}

// ---------------------------------------------------------------------------
// Kernel C: out[b,q,d] = sum_v attn[b,q,v] * inputs[b,v,d]
// double-buffered, k-vectorized LDS (unchanged from R7).
// BM=32(q), BN=64(d), BK=32(v), 256 threads, micro 2x4.
// grid: (8, 8, 4) = 256 CTAs -> 2 co-resident per SM.
// ---------------------------------------------------------------------------
__global__ void __launch_bounds__(256) av_kernel(
    const float* __restrict__ inp, float* __restrict__ out)
{
    __shared__ float As[2][32][36];   // stride 36: float4-aligned fills
    __shared__ float Is[2][32][64];

    const int t  = threadIdx.x;
    const int tx = t & 15;        // col group: cols tx*4 .. tx*4+3 (of 64)
    const int ty = t >> 4;        // row group: rows ty*2, ty*2+1 (of 32)
    const int b  = blockIdx.z;
    const int q0 = blockIdx.y * 32;
    const int d0 = blockIdx.x * 64;

    const int ar = t >> 3, ac4 = (t & 7) * 4;      // As: 1 float4/thread
    const int ir = t >> 4, ic4 = (t & 15) * 4;     // Is: 2 float4/thread

    float acc[2][4] = {};

    {
        *(float4*)&As[0][ar][ac4] =
            *(const float4*)&g_attn[((size_t)(b * TQ + q0 + ar)) * TV + ac4];
        *(float4*)&Is[0][ir][ic4] =
            *(const float4*)&inp[((size_t)(b * TV + ir)) * DD + d0 + ic4];
        *(float4*)&Is[0][ir + 16][ic4] =
            *(const float4*)&inp[((size_t)(b * TV + ir + 16)) * DD + d0 + ic4];
    }
    __syncthreads();

    for (int vt = 0; vt < TV / 32; ++vt) {
        const int cur = vt & 1;
        const bool has_next = (vt + 1 < TV / 32);
        float4 pA, pI0, pI1;
        if (has_next) {
            const int v0 = (vt + 1) * 32;
            pA  = *(const float4*)&g_attn[((size_t)(b * TQ + q0 + ar)) * TV + v0 + ac4];
            pI0 = *(const float4*)&inp[((size_t)(b * TV + v0 + ir)) * DD + d0 + ic4];
            pI1 = *(const float4*)&inp[((size_t)(b * TV + v0 + ir + 16)) * DD + d0 + ic4];
        }
#pragma unroll
        for (int k4 = 0; k4 < 32; k4 += 4) {
            float4 a0 = *(const float4*)&As[cur][ty * 2 + 0][k4];
            float4 a1 = *(const float4*)&As[cur][ty * 2 + 1][k4];
#pragma unroll
            for (int kk = 0; kk < 4; ++kk) {
                float4 iv = *(const float4*)&Is[cur][k4 + kk][tx * 4];
                float av0 = (&a0.x)[kk], av1 = (&a1.x)[kk];
                acc[0][0] = fmaf(av0, iv.x, acc[0][0]);
                acc[0][1] = fmaf(av0, iv.y, acc[0][1]);
                acc[0][2] = fmaf(av0, iv.z, acc[0][2]);
                acc[0][3] = fmaf(av0, iv.w, acc[0][3]);
                acc[1][0] = fmaf(av1, iv.x, acc[1][0]);
                acc[1][1] = fmaf(av1, iv.y, acc[1][1]);
                acc[1][2] = fmaf(av1, iv.z, acc[1][2]);
                acc[1][3] = fmaf(av1, iv.w, acc[1][3]);
            }
        }
        if (has_next) {
            const int nxt = cur ^ 1;
            *(float4*)&As[nxt][ar][ac4] = pA;
            *(float4*)&Is[nxt][ir][ic4] = pI0;
            *(float4*)&Is[nxt][ir + 16][ic4] = pI1;
            __syncthreads();
        }
    }

#pragma unroll
    for (int r = 0; r < 2; ++r) {
        float4 o;
        o.x = acc[r][0]; o.y = acc[r][1]; o.z = acc[r][2]; o.w = acc[r][3];
        *(float4*)&out[((size_t)(b * TQ + q0 + ty * 2 + r)) * DD + d0 + tx * 4] = o;
    }
}

// ---------------------------------------------------------------------------
extern "C" void kernel_launch(void* const* d_in, const int* in_sizes, int n_in,
                              void* d_out, int out_size)
{
    (void)in_sizes; (void)n_in; (void)out_size;
    const float* inputs  = (const float*)d_in[0];   // [B,Tv,D]
    const float* context = (const float*)d_in[1];   // [B,Tq,D]
    const int*   mask    = (const int*)  d_in[2];   // [B,Tv]
    const float* Wk      = (const float*)d_in[3];   // [D,A]
    const float* bk      = (const float*)d_in[4];   // [A]
    const float* Wq      = (const float*)d_in[5];   // [D,A]
    const float* bq      = (const float*)d_in[6];   // [A]
    const float* attn_v  = (const float*)d_in[7];   // [A]
    float* out = (float*)d_out;                     // [B,Tq,D]

    static const size_t smemB = SMEMB_FLOATS * sizeof(float);
    cudaFuncSetAttribute(score_softmax_kernel,
                         cudaFuncAttributeMaxDynamicSharedMemorySize, (int)smemB);

    // K = inputs @ Wk + bk ; Q = context @ Wq + bq  (fused, 320 CTAs x 128 thr)
    proj_kernel<<<PROJ_KBLKS + (BB * TQ) / 16, 128>>>(
        inputs, context, Wk, bk, Wq, bq);
    // scores + softmax -> g_attn
    {
        dim3 grid(TQ / 4, BB);
        score_softmax_kernel<<<grid, 256, smemB>>>(mask, attn_v);
    }
    // out = attn @ inputs
    {
        dim3 grid(DD / 64, TQ / 32, BB);
        av_kernel<<<grid, 256>>>(inputs, out);
    }
}

// round 13
// speedup vs baseline: 1.2661x; 1.0045x over previous
#include <cuda_runtime.h>
#include <cuda_bf16.h>
#include <cstdint>

// Problem dims (fixed by the dataset)
#define BB   4
#define TQ   256
#define TV   1024
#define DD   512
#define AA   128

// Scratch buffers (device globals: allocation-free)
__device__ float g_K[BB * TV * AA];      // 2 MB
__device__ float g_Q[BB * TQ * AA];      // 0.5 MB
__device__ float g_attn[BB * TQ * TV];   // 4 MB

// ---------------------------------------------------------------------------
// fast math helpers
// ---------------------------------------------------------------------------
__device__ __forceinline__ float fast_ex2(float x) {
    float y;
    asm("ex2.approx.f32 %0, %1;" : "=f"(y) : "f"(x));
    return y;
}
__device__ __forceinline__ float ftanh(float x) {
    float y;
    asm("tanh.approx.f32 %0, %1;" : "=f"(y) : "f"(x));
    return y;
}
// cp.async helpers (16B)
__device__ __forceinline__ void cp16(void* dst_smem, const void* src_gmem) {
    unsigned d = (unsigned)__cvta_generic_to_shared(dst_smem);
    asm volatile("cp.async.ca.shared.global [%0], [%1], 16;" :: "r"(d), "l"(src_gmem));
}
__device__ __forceinline__ void cp_commit() {
    asm volatile("cp.async.commit_group;");
}
__device__ __forceinline__ void cp_wait0() {
    asm volatile("cp.async.wait_group 0;");
}

// ---------------------------------------------------------------------------
// Kernel A: fused K/Q projection, cp.async double-buffered (unchanged R12).
// BM=16, BN=128, BK=32, 128 threads, micro 4x4. grid = 320 CTAs.
// ---------------------------------------------------------------------------
#define PROJ_KBLKS ((BB * TV) / 16)   // 256
#define PROJ_NTILES (DD / 32)         // 16

__global__ void __launch_bounds__(128) proj_kernel(
    const float* __restrict__ inputs, const float* __restrict__ context,
    const float* __restrict__ Wk, const float* __restrict__ bk,
    const float* __restrict__ Wq, const float* __restrict__ bq)
{
    __shared__ float Xs[2][16][32];
    __shared__ float Ws[2][32][128];

    const int bx = blockIdx.x;
    const bool isK = (bx < PROJ_KBLKS);
    const float* X    = isK ? inputs : context;
    const float* W    = isK ? Wk : Wq;
    const float* bias = isK ? bk : bq;
    float* out        = isK ? g_K : g_Q;
    const int r0 = (isK ? bx : (bx - PROJ_KBLKS)) * 16;

    const int t  = threadIdx.x;
    const int tx = t & 31;
    const int ty = t >> 5;

    const int xr = t >> 3, xc4 = (t & 7) * 4;

    float acc[4][4] = {};

    {
        cp16(&Xs[0][xr][xc4], &X[(size_t)(r0 + xr) * DD + xc4]);
#pragma unroll
        for (int i = 0; i < 8; ++i) {
            int f = i * 128 + t;
            int rr = f >> 5, c4 = (f & 31) * 4;
            cp16(&Ws[0][rr][c4], &W[(size_t)rr * AA + c4]);
        }
        cp_commit();
        cp_wait0();
    }
    __syncthreads();

    for (int kt = 0; kt < PROJ_NTILES; ++kt) {
        const int cur = kt & 1;
        const bool has_next = (kt + 1 < PROJ_NTILES);
        if (has_next) {
            const int k0 = (kt + 1) * 32;
            const int nxt = cur ^ 1;
            cp16(&Xs[nxt][xr][xc4], &X[(size_t)(r0 + xr) * DD + k0 + xc4]);
#pragma unroll
            for (int i = 0; i < 8; ++i) {
                int f = i * 128 + t;
                int rr = f >> 5, c4 = (f & 31) * 4;
                cp16(&Ws[nxt][rr][c4], &W[(size_t)(k0 + rr) * AA + c4]);
            }
            cp_commit();
        }
#pragma unroll
        for (int k4 = 0; k4 < 32; k4 += 4) {
            float4 xv[4];
#pragma unroll
            for (int r = 0; r < 4; ++r)
                xv[r] = *(const float4*)&Xs[cur][ty * 4 + r][k4];
#pragma unroll
            for (int kk = 0; kk < 4; ++kk) {
                float4 wv = *(const float4*)&Ws[cur][k4 + kk][tx * 4];
#pragma unroll
                for (int r = 0; r < 4; ++r) {
                    float xs = (&xv[r].x)[kk];
                    acc[r][0] = fmaf(xs, wv.x, acc[r][0]);
                    acc[r][1] = fmaf(xs, wv.y, acc[r][1]);
                    acc[r][2] = fmaf(xs, wv.z, acc[r][2]);
                    acc[r][3] = fmaf(xs, wv.w, acc[r][3]);
                }
            }
        }
        if (has_next) {
            cp_wait0();
            __syncthreads();
        }
    }

    float b0 = bias[tx * 4 + 0], b1 = bias[tx * 4 + 1];
    float b2 = bias[tx * 4 + 2], b3 = bias[tx * 4 + 3];
#pragma unroll
    for (int r = 0; r < 4; ++r) {
        float4 o;
        o.x = acc[r][0] + b0; o.y = acc[r][1] + b1;
        o.z = acc[r][2] + b2; o.w = acc[r][3] + b3;
        *(float4*)&out[(size_t)(r0 + ty * 4 + r) * AA + tx * 4] = o;
    }
}

// ---------------------------------------------------------------------------
// Kernel B: scores + softmax, cp.async double-buffered 64-v K tiles.
// grid: (TQ/4, B) = 256 CTAs, 256 threads, 2 CTAs/SM.
// Per tile: each thread owns one (q = t>>6, v = t&63) pair; 128 tanh.
// Ks rows v-major stride 132 (33x16B): cp16 fills aligned+coalesced,
// compute reads conflict-free (16B-chunk bank = 33v = v mod 32).
// ---------------------------------------------------------------------------
#define KS_STRIDE 132
#define SMEMB_FLOATS (2 * 64 * KS_STRIDE + 4 * 128 + 128 + 4 * 1024)

__global__ void __launch_bounds__(256, 2) score_softmax_kernel(
    const int* __restrict__ mask, const float* __restrict__ attn_v)
{
    extern __shared__ float sm[];
    float* Ks  = sm;                         // 2 x 64 x 132
    float* Qs  = Ks + 2 * 64 * KS_STRIDE;    // 512
    float* av  = Qs + 4 * 128;               // 128
    float* sc  = av + 128;                   // 4096

    const int t  = threadIdx.x;
    const int b  = blockIdx.y;
    const int q0 = blockIdx.x * 4;

    if (t < 128) {
        *(float4*)&Qs[t * 4] =
            *(const float4*)&g_Q[((size_t)(b * TQ + q0)) * AA + t * 4];
        av[t] = attn_v[t];
    }

    const int v0 = t & 63;         // this thread's v within the tile
    const int q  = t >> 6;         // 0..3

    // fill coordinates: 64x128 floats = 2048 float4, 8 per thread
    const float* Kb = g_K + (size_t)b * TV * AA;

    // prologue: tile 0 -> buffer 0
    {
#pragma unroll
        for (int i = 0; i < 8; ++i) {
            int f = i * 256 + t;
            int row = f >> 5, c4 = (f & 31) * 4;
            cp16(&Ks[row * KS_STRIDE + c4], &Kb[(size_t)row * AA + c4]);
        }
        cp_commit();
        cp_wait0();
    }
    __syncthreads();   // also covers Qs/av writes

    for (int vt = 0; vt < TV / 64; ++vt) {
        const int cur = vt & 1;
        const bool has_next = (vt + 1 < TV / 64);
        if (has_next) {   // prefetch next 64-v tile (buffer freed by the
                          // barrier that ended the previous iteration)
            const int nxt = cur ^ 1;
            const float* Kp = Kb + (size_t)(vt + 1) * 64 * AA;
            float* Kd = Ks + nxt * 64 * KS_STRIDE;
#pragma unroll
            for (int i = 0; i < 8; ++i) {
                int f = i * 256 + t;
                int row = f >> 5, c4 = (f & 31) * 4;
                cp16(&Kd[row * KS_STRIDE + c4], &Kp[(size_t)row * AA + c4]);
            }
            cp_commit();
        }

        float a0 = 0.f;
        const float* kp = Ks + cur * 64 * KS_STRIDE + v0 * KS_STRIDE;
        const float* qp = Qs + q * AA;
#pragma unroll 4
        for (int a4 = 0; a4 < AA; a4 += 4) {
            float4 k4 = *(const float4*)&kp[a4];
            float4 q4 = *(const float4*)&qp[a4];
            float4 w4 = *(const float4*)&av[a4];
            a0 = fmaf(w4.x, ftanh(q4.x + k4.x), a0);
            a0 = fmaf(w4.y, ftanh(q4.y + k4.y), a0);
            a0 = fmaf(w4.z, ftanh(q4.z + k4.z), a0);
            a0 = fmaf(w4.w, ftanh(q4.w + k4.w), a0);
        }
        sc[q * TV + vt * 64 + v0] = a0;

        if (has_next) {
            cp_wait0();
            __syncthreads();
        }
    }
    __syncthreads();

    const int w = t >> 5, lane = t & 31;
    if (w < 4) {
        float* row = sc + w * TV;
        const int* mrow = mask + (size_t)b * TV;
        float mx = -3.4e38f;
        for (int j = lane; j < TV; j += 32) {
            float s = row[j] + (1.0f - (float)mrow[j]) * (-1e9f);
            row[j] = s;
            mx = fmaxf(mx, s);
        }
#pragma unroll
        for (int o = 16; o; o >>= 1) mx = fmaxf(mx, __shfl_xor_sync(~0u, mx, o));
        float sum = 0.f;
        for (int j = lane; j < TV; j += 32) {
            float e = fast_ex2((row[j] - mx) * 1.4426950408889634f);
            row[j] = e;
            sum += e;
        }
#pragma unroll
        for (int o = 16; o; o >>= 1) sum += __shfl_xor_sync(~0u, sum, o);
        float inv = 1.0f / sum;
        float* arow = g_attn + ((size_t)(b * TQ + q0 + w)) * TV;
        for (int j = lane; j < TV; j += 32) arow[j] = row[j] * inv;
    }
}

// ---------------------------------------------------------------------------
// Kernel C: out[b,q,d] = sum_v attn[b,q,v] * inputs[b,v,d]
// cp.async double-buffered, k-vectorized LDS.
// BM=32(q), BN=64(d), BK=32(v), 256 threads, micro 2x4. grid: 256 CTAs.
// ---------------------------------------------------------------------------
__global__ void __launch_bounds__(256) av_kernel(
    const float* __restrict__ inp, float* __restrict__ out)
{
    __shared__ float As[2][32][36];   // stride 36: 16B-aligned rows
    __shared__ float Is[2][32][64];

    const int t  = threadIdx.x;
    const int tx = t & 15;
    const int ty = t >> 4;
    const int b  = blockIdx.z;
    const int q0 = blockIdx.y * 32;
    const int d0 = blockIdx.x * 64;

    const int ar = t >> 3, ac4 = (t & 7) * 4;      // As: 1 cp16/thread
    const int ir = t >> 4, ic4 = (t & 15) * 4;     // Is: 2 cp16/thread

    float acc[2][4] = {};

    {
        cp16(&As[0][ar][ac4],
             &g_attn[((size_t)(b * TQ + q0 + ar)) * TV + ac4]);
        cp16(&Is[0][ir][ic4],
             &inp[((size_t)(b * TV + ir)) * DD + d0 + ic4]);
        cp16(&Is[0][ir + 16][ic4],
             &inp[((size_t)(b * TV + ir + 16)) * DD + d0 + ic4]);
        cp_commit();
        cp_wait0();
    }
    __syncthreads();

    for (int vt = 0; vt < TV / 32; ++vt) {
        const int cur = vt & 1;
        const bool has_next = (vt + 1 < TV / 32);
        if (has_next) {
            const int v0 = (vt + 1) * 32;
            const int nxt = cur ^ 1;
            cp16(&As[nxt][ar][ac4],
                 &g_attn[((size_t)(b * TQ + q0 + ar)) * TV + v0 + ac4]);
            cp16(&Is[nxt][ir][ic4],
                 &inp[((size_t)(b * TV + v0 + ir)) * DD + d0 + ic4]);
            cp16(&Is[nxt][ir + 16][ic4],
                 &inp[((size_t)(b * TV + v0 + ir + 16)) * DD + d0 + ic4]);
            cp_commit();
        }
#pragma unroll
        for (int k4 = 0; k4 < 32; k4 += 4) {
            float4 a0 = *(const float4*)&As[cur][ty * 2 + 0][k4];
            float4 a1 = *(const float4*)&As[cur][ty * 2 + 1][k4];
#pragma unroll
            for (int kk = 0; kk < 4; ++kk) {
                float4 iv = *(const float4*)&Is[cur][k4 + kk][tx * 4];
                float av0 = (&a0.x)[kk], av1 = (&a1.x)[kk];
                acc[0][0] = fmaf(av0, iv.x, acc[0][0]);
                acc[0][1] = fmaf(av0, iv.y, acc[0][1]);
                acc[0][2] = fmaf(av0, iv.z, acc[0][2]);
                acc[0][3] = fmaf(av0, iv.w, acc[0][3]);
                acc[1][0] = fmaf(av1, iv.x, acc[1][0]);
                acc[1][1] = fmaf(av1, iv.y, acc[1][1]);
                acc[1][2] = fmaf(av1, iv.z, acc[1][2]);
                acc[1][3] = fmaf(av1, iv.w, acc[1][3]);
            }
        }
        if (has_next) {
            cp_wait0();
            __syncthreads();
        }
    }

#pragma unroll
    for (int r = 0; r < 2; ++r) {
        float4 o;
        o.x = acc[r][0]; o.y = acc[r][1]; o.z = acc[r][2]; o.w = acc[r][3];
        *(float4*)&out[((size_t)(b * TQ + q0 + ty * 2 + r)) * DD + d0 + tx * 4] = o;
    }
}

// ---------------------------------------------------------------------------
extern "C" void kernel_launch(void* const* d_in, const int* in_sizes, int n_in,
                              void* d_out, int out_size)
{
    (void)in_sizes; (void)n_in; (void)out_size;
    const float* inputs  = (const float*)d_in[0];   // [B,Tv,D]
    const float* context = (const float*)d_in[1];   // [B,Tq,D]
    const int*   mask    = (const int*)  d_in[2];   // [B,Tv]
    const float* Wk      = (const float*)d_in[3];   // [D,A]
    const float* bk      = (const float*)d_in[4];   // [A]
    const float* Wq      = (const float*)d_in[5];   // [D,A]
    const float* bq      = (const float*)d_in[6];   // [A]
    const float* attn_v  = (const float*)d_in[7];   // [A]
    float* out = (float*)d_out;                     // [B,Tq,D]

    static const size_t smemB = SMEMB_FLOATS * sizeof(float);
    cudaFuncSetAttribute(score_softmax_kernel,
                         cudaFuncAttributeMaxDynamicSharedMemorySize, (int)smemB);

    // K = inputs @ Wk + bk ; Q = context @ Wq + bq  (fused, 320 CTAs x 128 thr)
    proj_kernel<<<PROJ_KBLKS + (BB * TQ) / 16, 128>>>(
        inputs, context, Wk, bk, Wq, bq);
    // scores + softmax -> g_attn
    {
        dim3 grid(TQ / 4, BB);
        score_softmax_kernel<<<grid, 256, smemB>>>(mask, attn_v);
    }
    // out = attn @ inputs
    {
        dim3 grid(DD / 64, TQ / 32, BB);
        av_kernel<<<grid, 256>>>(inputs, out);
    }
}

// round 15
// speedup vs baseline: 1.9503x; 1.5404x over previous
#include <cuda_runtime.h>
#include <cuda_bf16.h>
#include <cstdint>

// Problem dims (fixed by the dataset)
#define BB   4
#define TQ   256
#define TV   1024
#define DD   512
#define AA   128

// Scratch buffers (device globals: allocation-free)
__device__ float g_K[BB * TV * AA];      // 2 MB
__device__ float g_Q[BB * TQ * AA];      // 0.5 MB
__device__ float g_attn[BB * TQ * TV];   // 4 MB

// ---------------------------------------------------------------------------
// fast math helpers
// ---------------------------------------------------------------------------
__device__ __forceinline__ float fast_ex2(float x) {
    float y;
    asm("ex2.approx.f32 %0, %1;" : "=f"(y) : "f"(x));
    return y;
}
__device__ __forceinline__ float ftanh(float x) {
    float y;
    asm("tanh.approx.f32 %0, %1;" : "=f"(y) : "f"(x));
    return y;
}
// cp.async helpers (16B)
__device__ __forceinline__ void cp16(void* dst_smem, const void* src_gmem) {
    unsigned d = (unsigned)__cvta_generic_to_shared(dst_smem);
    asm volatile("cp.async.ca.shared.global [%0], [%1], 16;" :: "r"(d), "l"(src_gmem));
}
__device__ __forceinline__ void cp_commit() {
    asm volatile("cp.async.commit_group;");
}
__device__ __forceinline__ void cp_wait0() {
    asm volatile("cp.async.wait_group 0;");
}
// tf32 helpers
__device__ __forceinline__ uint32_t f2tf32(float x) {
    uint32_t r;
    asm("cvt.rna.tf32.f32 %0, %1;" : "=r"(r) : "f"(x));
    return r;
}
__device__ __forceinline__ void mma_tf32(float4& d,
    uint32_t a0, uint32_t a1, uint32_t a2, uint32_t a3,
    uint32_t b0, uint32_t b1)
{
    asm volatile(
        "mma.sync.aligned.m16n8k8.row.col.f32.tf32.tf32.f32 "
        "{%0,%1,%2,%3}, {%4,%5,%6,%7}, {%8,%9}, {%0,%1,%2,%3};"
        : "+f"(d.x), "+f"(d.y), "+f"(d.z), "+f"(d.w)
        : "r"(a0), "r"(a1), "r"(a2), "r"(a3), "r"(b0), "r"(b1));
}

// ---------------------------------------------------------------------------
// Shared tf32 GEMM tile body: CTA = 128 threads = 2x2 warps.
// CTA tile 32(M) x 64(N), warp tile 16x32 (1 m16 x 4 n8 mma tiles).
// K consumed in 32-wide chunks, cp.async double-buffered.
// As[2][32][36] row-major (m,k); Bs[2][32][72] row-major (k,n).
// ---------------------------------------------------------------------------
#define AS_STRIDE 36
#define BS_STRIDE 72

struct MmaSmem {
    float As[2][32][AS_STRIDE];
    float Bs[2][32][BS_STRIDE];
};

// One GEMM: out[m0.., n0..] (+bias if not null) = A[M,K] x B[K,N]
// lda/ldb/ldo: row strides. nchunks = K/32.
__device__ __forceinline__ void gemm_tile_tf32(
    MmaSmem* s,
    const float* __restrict__ A, int lda,
    const float* __restrict__ B, int ldb,
    float* __restrict__ out, int ldo,
    const float* __restrict__ bias,    // may be nullptr
    int m0, int n0, int nchunks)
{
    const int t    = threadIdx.x;
    const int lane = t & 31;
    const int gID  = lane >> 2;      // 0..7
    const int tig  = lane & 3;       // 0..3
    const int wm   = (t >> 5) >> 1;  // 0,1
    const int wn   = (t >> 5) & 1;   // 0,1

    // fill coords
    // As: 32 rows x 32 floats = 256 f4; ar in [0,16), +16 second half
    const int ar = t >> 3, ac4 = (t & 7) * 4;
    // Bs: 32 rows x 64 floats = 512 f4; br in [0,8), +8/+16/+24
    const int br = t >> 4, bc4 = (t & 15) * 4;

    float4 acc[4] = {};

    // prologue: chunk 0 -> buffer 0
    {
        cp16(&s->As[0][ar][ac4],      &A[(size_t)(m0 + ar) * lda + ac4]);
        cp16(&s->As[0][ar + 16][ac4], &A[(size_t)(m0 + ar + 16) * lda + ac4]);
#pragma unroll
        for (int i = 0; i < 4; ++i)
            cp16(&s->Bs[0][br + i * 8][bc4],
                 &B[(size_t)(br + i * 8) * ldb + n0 + bc4]);
        cp_commit();
        cp_wait0();
    }
    __syncthreads();

    for (int kc = 0; kc < nchunks; ++kc) {
        const int cur = kc & 1;
        const bool has_next = (kc + 1 < nchunks);
        if (has_next) {
            const int k0 = (kc + 1) * 32;
            const int nxt = cur ^ 1;
            cp16(&s->As[nxt][ar][ac4],      &A[(size_t)(m0 + ar) * lda + k0 + ac4]);
            cp16(&s->As[nxt][ar + 16][ac4], &A[(size_t)(m0 + ar + 16) * lda + k0 + ac4]);
#pragma unroll
            for (int i = 0; i < 4; ++i)
                cp16(&s->Bs[nxt][br + i * 8][bc4],
                     &B[(size_t)(k0 + br + i * 8) * ldb + n0 + bc4]);
            cp_commit();
        }
        const int ar0 = wm * 16 + gID;
#pragma unroll
        for (int k8 = 0; k8 < 32; k8 += 8) {
            uint32_t a0 = f2tf32(s->As[cur][ar0][k8 + tig]);
            uint32_t a1 = f2tf32(s->As[cur][ar0 + 8][k8 + tig]);
            uint32_t a2 = f2tf32(s->As[cur][ar0][k8 + tig + 4]);
            uint32_t a3 = f2tf32(s->As[cur][ar0 + 8][k8 + tig + 4]);
#pragma unroll
            for (int nt = 0; nt < 4; ++nt) {
                const int nc = wn * 32 + nt * 8 + gID;
                uint32_t b0 = f2tf32(s->Bs[cur][k8 + tig][nc]);
                uint32_t b1 = f2tf32(s->Bs[cur][k8 + tig + 4][nc]);
                mma_tf32(acc[nt], a0, a1, a2, a3, b0, b1);
            }
        }
        if (has_next) {
            cp_wait0();
            __syncthreads();
        }
    }

    // epilogue: D frag rows (gID, gID+8), cols (2*tig, 2*tig+1)
    const int orow = m0 + wm * 16 + gID;
#pragma unroll
    for (int nt = 0; nt < 4; ++nt) {
        const int col = n0 + wn * 32 + nt * 8 + tig * 2;
        float2 bv = make_float2(0.f, 0.f);
        if (bias) bv = *(const float2*)&bias[col];
        float2 lo = make_float2(acc[nt].x + bv.x, acc[nt].y + bv.y);
        float2 hi = make_float2(acc[nt].z + bv.x, acc[nt].w + bv.y);
        *(float2*)&out[(size_t)orow * ldo + col] = lo;
        *(float2*)&out[(size_t)(orow + 8) * ldo + col] = hi;
    }
}

// ---------------------------------------------------------------------------
// Kernel A: fused K/Q projection via tf32 mma.
// M = 4096 (K) + 1024 (Q), N = 128, K = 512.
// CTA tile 32x64 -> grid = 256 + 64 = 320 CTAs, 128 threads.
// ---------------------------------------------------------------------------
#define PROJ_KCTAS 256   // 128 m-blocks x 2 n-blocks

__global__ void __launch_bounds__(128) proj_kernel(
    const float* __restrict__ inputs, const float* __restrict__ context,
    const float* __restrict__ Wk, const float* __restrict__ bk,
    const float* __restrict__ Wq, const float* __restrict__ bq)
{
    __shared__ MmaSmem s;

    const int bx = blockIdx.x;
    const bool isK = (bx < PROJ_KCTAS);
    const int lx = isK ? bx : (bx - PROJ_KCTAS);
    const float* X    = isK ? inputs : context;
    const float* W    = isK ? Wk : Wq;
    const float* bias = isK ? bk : bq;
    float* out        = isK ? g_K : g_Q;
    const int m0 = (lx >> 1) * 32;
    const int n0 = (lx & 1) * 64;

    gemm_tile_tf32(&s, X, DD, W, AA, out, AA, bias, m0, n0, DD / 32);
}

// ---------------------------------------------------------------------------
// Kernel B: scores + softmax (unchanged from R13).
// ---------------------------------------------------------------------------
#define KS_STRIDE 132
#define SMEMB_FLOATS (2 * 64 * KS_STRIDE + 4 * 128 + 128 + 4 * 1024)

__global__ void __launch_bounds__(256, 2) score_softmax_kernel(
    const int* __restrict__ mask, const float* __restrict__ attn_v)
{
    extern __shared__ float sm[];
    float* Ks  = sm;                         // 2 x 64 x 132
    float* Qs  = Ks + 2 * 64 * KS_STRIDE;    // 512
    float* av  = Qs + 4 * 128;               // 128
    float* sc  = av + 128;                   // 4096

    const int t  = threadIdx.x;
    const int b  = blockIdx.y;
    const int q0 = blockIdx.x * 4;

    if (t < 128) {
        *(float4*)&Qs[t * 4] =
            *(const float4*)&g_Q[((size_t)(b * TQ + q0)) * AA + t * 4];
        av[t] = attn_v[t];
    }

    const int v0 = t & 63;
    const int q  = t >> 6;

    const float* Kb = g_K + (size_t)b * TV * AA;

    {
#pragma unroll
        for (int i = 0; i < 8; ++i) {
            int f = i * 256 + t;
            int row = f >> 5, c4 = (f & 31) * 4;
            cp16(&Ks[row * KS_STRIDE + c4], &Kb[(size_t)row * AA + c4]);
        }
        cp_commit();
        cp_wait0();
    }
    __syncthreads();

    for (int vt = 0; vt < TV / 64; ++vt) {
        const int cur = vt & 1;
        const bool has_next = (vt + 1 < TV / 64);
        if (has_next) {
            const int nxt = cur ^ 1;
            const float* Kp = Kb + (size_t)(vt + 1) * 64 * AA;
            float* Kd = Ks + nxt * 64 * KS_STRIDE;
#pragma unroll
            for (int i = 0; i < 8; ++i) {
                int f = i * 256 + t;
                int row = f >> 5, c4 = (f & 31) * 4;
                cp16(&Kd[row * KS_STRIDE + c4], &Kp[(size_t)row * AA + c4]);
            }
            cp_commit();
        }

        float a0 = 0.f;
        const float* kp = Ks + cur * 64 * KS_STRIDE + v0 * KS_STRIDE;
        const float* qp = Qs + q * AA;
#pragma unroll 4
        for (int a4 = 0; a4 < AA; a4 += 4) {
            float4 k4 = *(const float4*)&kp[a4];
            float4 q4 = *(const float4*)&qp[a4];
            float4 w4 = *(const float4*)&av[a4];
            a0 = fmaf(w4.x, ftanh(q4.x + k4.x), a0);
            a0 = fmaf(w4.y, ftanh(q4.y + k4.y), a0);
            a0 = fmaf(w4.z, ftanh(q4.z + k4.z), a0);
            a0 = fmaf(w4.w, ftanh(q4.w + k4.w), a0);
        }
        sc[q * TV + vt * 64 + v0] = a0;

        if (has_next) {
            cp_wait0();
            __syncthreads();
        }
    }
    __syncthreads();

    const int w = t >> 5, lane = t & 31;
    if (w < 4) {
        float* row = sc + w * TV;
        const int* mrow = mask + (size_t)b * TV;
        float mx = -3.4e38f;
        for (int j = lane; j < TV; j += 32) {
            float s = row[j] + (1.0f - (float)mrow[j]) * (-1e9f);
            row[j] = s;
            mx = fmaxf(mx, s);
        }
#pragma unroll
        for (int o = 16; o; o >>= 1) mx = fmaxf(mx, __shfl_xor_sync(~0u, mx, o));
        float sum = 0.f;
        for (int j = lane; j < TV; j += 32) {
            float e = fast_ex2((row[j] - mx) * 1.4426950408889634f);
            row[j] = e;
            sum += e;
        }
#pragma unroll
        for (int o = 16; o; o >>= 1) sum += __shfl_xor_sync(~0u, sum, o);
        float inv = 1.0f / sum;
        float* arow = g_attn + ((size_t)(b * TQ + q0 + w)) * TV;
        for (int j = lane; j < TV; j += 32) arow[j] = row[j] * inv;
    }
}

// ---------------------------------------------------------------------------
// Kernel C: out = attn @ inputs via tf32 mma.
// Per batch: M=256(q), K=1024(v), N=512(d). CTA tile 32x64.
// grid (DD/64=8, TQ/32=8, BB=4) = 256 CTAs, 128 threads.
// ---------------------------------------------------------------------------
__global__ void __launch_bounds__(128) av_kernel(
    const float* __restrict__ inp, float* __restrict__ out)
{
    __shared__ MmaSmem s;

    const int b  = blockIdx.z;
    const int m0 = blockIdx.y * 32;
    const int n0 = blockIdx.x * 64;

    const float* A = g_attn + (size_t)b * TQ * TV;   // [256, 1024]
    const float* B = inp    + (size_t)b * TV * DD;   // [1024, 512]
    float* O       = out    + (size_t)b * TQ * DD;   // [256, 512]

    gemm_tile_tf32(&s, A, TV, B, DD, O, DD, nullptr, m0, n0, TV / 32);
}

// ---------------------------------------------------------------------------
extern "C" void kernel_launch(void* const* d_in, const int* in_sizes, int n_in,
                              void* d_out, int out_size)
{
    (void)in_sizes; (void)n_in; (void)out_size;
    const float* inputs  = (const float*)d_in[0];   // [B,Tv,D]
    const float* context = (const float*)d_in[1];   // [B,Tq,D]
    const int*   mask    = (const int*)  d_in[2];   // [B,Tv]
    const float* Wk      = (const float*)d_in[3];   // [D,A]
    const float* bk      = (const float*)d_in[4];   // [A]
    const float* Wq      = (const float*)d_in[5];   // [D,A]
    const float* bq      = (const float*)d_in[6];   // [A]
    const float* attn_v  = (const float*)d_in[7];   // [A]
    float* out = (float*)d_out;                     // [B,Tq,D]

    static const size_t smemB = SMEMB_FLOATS * sizeof(float);
    cudaFuncSetAttribute(score_softmax_kernel,
                         cudaFuncAttributeMaxDynamicSharedMemorySize, (int)smemB);

    // K = inputs @ Wk + bk ; Q = context @ Wq + bq  (tf32 mma, 320 CTAs)
    proj_kernel<<<PROJ_KCTAS + 64, 128>>>(inputs, context, Wk, bk, Wq, bq);
    // scores + softmax -> g_attn
    {
        dim3 grid(TQ / 4, BB);
        score_softmax_kernel<<<grid, 256, smemB>>>(mask, attn_v);
    }
    // out = attn @ inputs  (tf32 mma, 256 CTAs)
    {
        dim3 grid(DD / 64, TQ / 32, BB);
        av_kernel<<<grid, 128>>>(inputs, out);
    }
}